// round 9
// baseline (speedup 1.0000x reference)
#include <cuda_runtime.h>

// EMA y_t = (1-w)*y_{t-1} + w*x_t — decoupled-lookback scan, v7.
// = v3 (best: 63us) with the 32-entry stash moved from RF to smem, used as
// PRIVATE per-thread spill space (each thread writes/reads only its own
// column -> no __syncthreads anywhere). Regs ~64 -> ~32, so occupancy goes
// from the 50% RF cap to ~87% (7 CTAs/SM, smem-limited), which is what
// achieved-DRAM-BW tracked across v1..v6. Traffic stays single-read.
// Stash holds zero-entry partials so Phase C is dependency-free.

#define TT   8192
#define CC   256
#define LL   32
#define NCH  (TT / LL)   // 256 chunks per batch row
#define MAXB 16

// packed carry: high 32 = flag (0 empty / 1 aggregate / 2 inclusive prefix),
// low 32 = float payload. Zeroed each launch.
__device__ unsigned long long g_carry[MAXB * NCH * CC];

__global__ void ema_clear_kernel(int n2) {
    int i = blockIdx.x * blockDim.x + threadIdx.x;
    if (i < n2) ((ulonglong2*)g_carry)[i] = make_ulonglong2(0ULL, 0ULL);
}

__global__ __launch_bounds__(CC, 7) void ema_scan_kernel(
    const float* __restrict__ x,
    const float* __restrict__ y0,
    const float* __restrict__ smooth,
    float* __restrict__ out,
    int B)
{
    // private per-thread stash: [row][tid] -> warp lanes hit consecutive
    // 4B words (conflict-free); no cross-thread sharing, no syncs.
    __shared__ float s_ys[LL][CC];

    // batch-fast: predecessor (k-1,b) is exactly B bids lower; a ~1036-CTA
    // wave spans only ~65 chunk-levels -> short lookback chains.
    const int b = blockIdx.x % B;
    const int k = blockIdx.x / B;
    const int c = threadIdx.x;

    const float w = fminf(fmaxf(smooth[c], 0.0f), 1.0f);
    const float a = 1.0f - w;

    // ---- Phase A: single read of the chunk; stash the zero-entry partial
    //      scan ys[i] = sum_{j<=i} a^(i-j) w x_j into smem. ----
    const float* xp = x + ((size_t)(b * TT + k * LL) * CC + c);
    float e = 0.0f;
#pragma unroll
    for (int i = 0; i < LL; i++) {
        e = fmaf(a, e, w * __ldcs(xp + i * CC));
        s_ys[i][c] = e;
    }

    // A_L = a^32 via 5 squarings
    float A2 = a * a;
    float A4 = A2 * A2;
    float A8 = A4 * A4;
    float A16 = A8 * A8;
    const float AL = A16 * A16;

    volatile unsigned long long* cb = g_carry + (size_t)(b * NCH) * CC;

    // publish aggregate (flag=1): aligned 8B store = atomic, no fence needed
    cb[(size_t)k * CC + c] =
        (1ULL << 32) | (unsigned long long)__float_as_uint(e);

    // ---- Lookback: fold predecessor aggregates, short-circuit on prefixes ----
    float acc;
    if (k == 0) {
        acc = y0[b * CC + c];
    } else {
        acc = 0.0f;
        float m = 1.0f;
        int j = k - 1;
        bool done = false;
        while (!done) {
            const int g = (j + 1 < 8) ? (j + 1) : 8;
            unsigned long long v[8];
            bool allset;
            do {  // batched spin: 8 independent volatile 8B reads per round
                allset = true;
#pragma unroll
                for (int u = 0; u < 8; u++) {
                    if (u < g) {
                        v[u] = cb[(size_t)(j - u) * CC + c];
                        if ((unsigned)(v[u] >> 32) == 0u) allset = false;
                    }
                }
            } while (!allset);
#pragma unroll
            for (int u = 0; u < 8; u++) {
                if (u < g) {
                    const unsigned f = (unsigned)(v[u] >> 32);
                    const float val = __uint_as_float((unsigned)(v[u] & 0xFFFFFFFFu));
                    acc = fmaf(m, val, acc);
                    if (f == 2u) { done = true; break; }  // inclusive prefix
                    m *= AL;                              // zero-start aggregate
                }
            }
            if (!done) {
                j -= g;
                if (j < 0) {  // all aggregates folded; add initial-state term
                    acc = fmaf(m, y0[b * CC + c], acc);
                    done = true;
                }
            }
        }
    }

    // publish inclusive prefix (flag=2) so downstream chunks short-circuit
    const float P = fmaf(AL, acc, e);
    cb[(size_t)k * CC + c] =
        (2ULL << 32) | (unsigned long long)__float_as_uint(P);

    // ---- Phase C: dependency-free fixup from the smem stash, stream out ----
    float* op = out + ((size_t)(b * TT + k * LL) * CC + c);
    float pw = a;   // a^(i+1)
#pragma unroll
    for (int i = 0; i < LL; i++) {
        __stcs(op + i * CC, fmaf(pw, acc, s_ys[i][c]));
        pw *= a;
    }
}

extern "C" void kernel_launch(void* const* d_in, const int* in_sizes, int n_in,
                              void* d_out, int out_size) {
    const float* x      = (const float*)d_in[0];  // [B, T, C]
    const float* y0     = (const float*)d_in[1];  // [B, C]
    const float* smooth = (const float*)d_in[2];  // [C]
    float* out          = (float*)d_out;

    const int B = in_sizes[0] / (TT * CC);

    const int n2 = (B * NCH * CC) / 2;            // ulonglong2 words
    ema_clear_kernel<<<(n2 + 255) / 256, 256>>>(n2);
    ema_scan_kernel<<<B * NCH, CC>>>(x, y0, smooth, out, B);
}

// round 11
// speedup vs baseline: 1.2861x; 1.2861x over previous
#include <cuda_runtime.h>

// EMA y_t = (1-w)*y_{t-1} + w*x_t — decoupled-lookback scan, v8.
// = v3 (best) with Phase A loads issued in groups of 8 (the one structural
// feature of v4, the only version to reach 4.5TB/s). Caps front-batched
// MLP_p1 at 8 to curb cross-CTA L1tex-queue contention spread
// (B300 model: spr 1.4 -> 1.15). Stash of zero-entry partials in regs;
// Phase C is a dependency-free fixup with two parallel power chains.

#define TT   8192
#define CC   256
#define LL   32
#define NCH  (TT / LL)   // 256 chunks per batch row
#define MAXB 16

// packed carry: high 32 = flag (0 empty / 1 aggregate / 2 inclusive prefix),
// low 32 = float payload. Zeroed each launch.
__device__ unsigned long long g_carry[MAXB * NCH * CC];

__global__ void ema_clear_kernel(int n2) {
    int i = blockIdx.x * blockDim.x + threadIdx.x;
    if (i < n2) ((ulonglong2*)g_carry)[i] = make_ulonglong2(0ULL, 0ULL);
}

__global__ __launch_bounds__(CC, 4) void ema_scan_kernel(
    const float* __restrict__ x,
    const float* __restrict__ y0,
    const float* __restrict__ smooth,
    float* __restrict__ out,
    int B)
{
    // batch-fast: predecessor (k-1,b) is exactly B bids lower; a ~592-CTA
    // wave spans only ~37 chunk-levels -> short lookback chains.
    const int b = blockIdx.x % B;
    const int k = blockIdx.x / B;
    const int c = threadIdx.x;

    const float w = fminf(fmaxf(smooth[c], 0.0f), 1.0f);
    const float a = 1.0f - w;

    // ---- Phase A: single read of the chunk in GROUPS OF 8 (bounded MLP),
    //      stash zero-entry partials ys[i] = sum_{j<=i} a^(i-j) w x_j. ----
    const float* xp = x + ((size_t)(b * TT + k * LL) * CC + c);
    float ys[LL];
    float e = 0.0f;
#pragma unroll
    for (int g8 = 0; g8 < LL / 8; g8++) {
        float v[8];
#pragma unroll
        for (int i = 0; i < 8; i++) v[i] = __ldcs(xp + (g8 * 8 + i) * CC);
#pragma unroll
        for (int i = 0; i < 8; i++) {
            e = fmaf(a, e, w * v[i]);
            ys[g8 * 8 + i] = e;
        }
    }

    // A_L = a^32 via 5 squarings
    float A2 = a * a;
    float A4 = A2 * A2;
    float A8 = A4 * A4;
    float A16 = A8 * A8;
    const float AL = A16 * A16;

    volatile unsigned long long* cb = g_carry + (size_t)(b * NCH) * CC;

    // publish aggregate (flag=1): aligned 8B store = atomic, no fence needed
    cb[(size_t)k * CC + c] =
        (1ULL << 32) | (unsigned long long)__float_as_uint(e);

    // ---- Lookback: fold predecessor aggregates, short-circuit on prefixes ----
    float acc;
    if (k == 0) {
        acc = y0[b * CC + c];
    } else {
        acc = 0.0f;
        float m = 1.0f;
        int j = k - 1;
        bool done = false;
        while (!done) {
            const int g = (j + 1 < 8) ? (j + 1) : 8;
            unsigned long long v[8];
            bool allset;
            do {  // batched spin: 8 independent volatile 8B reads per round
                allset = true;
#pragma unroll
                for (int u = 0; u < 8; u++) {
                    if (u < g) {
                        v[u] = cb[(size_t)(j - u) * CC + c];
                        if ((unsigned)(v[u] >> 32) == 0u) allset = false;
                    }
                }
            } while (!allset);
#pragma unroll
            for (int u = 0; u < 8; u++) {
                if (u < g) {
                    const unsigned f = (unsigned)(v[u] >> 32);
                    const float val = __uint_as_float((unsigned)(v[u] & 0xFFFFFFFFu));
                    acc = fmaf(m, val, acc);
                    if (f == 2u) { done = true; break; }  // inclusive prefix
                    m *= AL;                              // zero-start aggregate
                }
            }
            if (!done) {
                j -= g;
                if (j < 0) {  // all aggregates folded; add initial-state term
                    acc = fmaf(m, y0[b * CC + c], acc);
                    done = true;
                }
            }
        }
    }

    // publish inclusive prefix (flag=2) so downstream chunks short-circuit
    const float P = fmaf(AL, acc, e);
    cb[(size_t)k * CC + c] =
        (2ULL << 32) | (unsigned long long)__float_as_uint(P);

    // ---- Phase C: dependency-free fixup from the stash, stream outputs.
    //      Two independent a^(i+1) chains so stores aren't serialized. ----
    float* op = out + ((size_t)(b * TT + k * LL) * CC + c);
    float pwA = a;        // a^(2i+1) chain
    float pwB = a * a;    // a^(2i+2) chain
#pragma unroll
    for (int i = 0; i < LL / 2; i++) {
        __stcs(op + (2 * i) * CC,     fmaf(pwA, acc, ys[2 * i]));
        __stcs(op + (2 * i + 1) * CC, fmaf(pwB, acc, ys[2 * i + 1]));
        pwA *= A2;
        pwB *= A2;
    }
}

extern "C" void kernel_launch(void* const* d_in, const int* in_sizes, int n_in,
                              void* d_out, int out_size) {
    const float* x      = (const float*)d_in[0];  // [B, T, C]
    const float* y0     = (const float*)d_in[1];  // [B, C]
    const float* smooth = (const float*)d_in[2];  // [C]
    float* out          = (float*)d_out;

    const int B = in_sizes[0] / (TT * CC);

    const int n2 = (B * NCH * CC) / 2;            // ulonglong2 words
    ema_clear_kernel<<<(n2 + 255) / 256, 256>>>(n2);
    ema_scan_kernel<<<B * NCH, CC>>>(x, y0, smooth, out, B);
}